// round 14
// baseline (speedup 1.0000x reference)
#include <cuda_runtime.h>
#include <cstdint>

typedef unsigned long long u64;

#define FULLMASK 0xffffffffu

namespace {
constexpr int HT = 1024, WD = 1024;   // input H, W
constexpr int OH = 1018, OW = 1018;   // conv output H, W (pad=1, k=9)
constexpr int NB = 16;                // batch
constexpr int NCH = 16;               // vertical chunks
constexpr int CH  = 64;               // rows per chunk (last chunk = 58; both even)
constexpr int NSTRIP = 9;             // horizontal strips of 116 outputs
constexpr int TOTW = NSTRIP * NCH * NB;   // 2304 warps
constexpr int NBLK = TOTW / 4;            // 576 blocks @ 4 blk/SM
constexpr int NSLOT = 13;             // ring slots: 11 live rows + 2 free write targets
constexpr int RING_BYTES = 4 * 2 * NSLOT * 32 * 16;   // 53,248 B/block (dynamic)
constexpr float INV81 = 1.0f / 81.0f;
constexpr float EPSF  = 2.220446049250313e-16f;  // np.finfo(float64).eps
}

__device__ float g_cc, g_dx, g_dy;
__device__ unsigned g_cnt;

// ---------- packed f32x2 helpers ----------
__device__ __forceinline__ u64 pk(float lo, float hi) {
    u64 r; asm("mov.b64 %0,{%1,%2};" : "=l"(r) : "f"(lo), "f"(hi)); return r;
}
__device__ __forceinline__ void upk(u64 v, float& lo, float& hi) {
    asm("mov.b64 {%0,%1},%2;" : "=f"(lo), "=f"(hi) : "l"(v));
}
__device__ __forceinline__ u64 fadd2(u64 a, u64 b) {
    u64 r; asm("add.rn.f32x2 %0,%1,%2;" : "=l"(r) : "l"(a), "l"(b)); return r;
}
__device__ __forceinline__ u64 fmul2(u64 a, u64 b) {
    u64 r; asm("mul.rn.f32x2 %0,%1,%2;" : "=l"(r) : "l"(a), "l"(b)); return r;
}
__device__ __forceinline__ u64 ffma2(u64 a, u64 b, u64 c) {
    u64 r; asm("fma.rn.f32x2 %0,%1,%2,%3;" : "=l"(r) : "l"(a), "l"(b), "l"(c)); return r;
}
__device__ __forceinline__ u64 fsub2(u64 a, u64 b, u64 m1) { return ffma2(b, m1, a); }

__device__ __forceinline__ float frcp(float x) {
    float r; asm("rcp.approx.f32 %0,%1;" : "=f"(r) : "f"(x)); return r;
}

__device__ __forceinline__ uint32_t smem_u32(const void* p) {
    uint32_t a;
    asm("{ .reg .u64 t; cvta.to.shared.u64 t, %1; cvt.u32.u64 %0, t; }" : "=r"(a) : "l"(p));
    return a;
}
__device__ __forceinline__ void cpa16(uint32_t d, const float* s, int sz) {
    asm volatile("cp.async.cg.shared.global [%0], [%1], 16, %2;"
                 :: "r"(d), "l"(s), "r"(sz) : "memory");
}
#define CPA_COMMIT() asm volatile("cp.async.commit_group;" ::: "memory")
#define CPA_WAIT1()  asm volatile("cp.async.wait_group 1;" ::: "memory")
#define CPA_WAIT2()  asm volatile("cp.async.wait_group 2;" ::: "memory")
#define CPA_WAIT0()  asm volatile("cp.async.wait_group 0;" ::: "memory")

// horizontal 9-window sums (window = cols x-1..x+7) for 4 owned columns
__device__ __forceinline__ void hasm(u64 A, u64 B, u64 m1, u64& H01, u64& H23) {
    float c0, c1, c2, c3;
    upk(A, c0, c1); upk(B, c2, c3);
    float s2 = c0 + c1;
    float s3 = s2 + c2;
    float a  = s3 + c3;
    float aP1  = __shfl_down_sync(FULLMASK, a, 1);
    float c3M1 = __shfl_up_sync(FULLMASK, c3, 1);
    float c0P2 = __shfl_down_sync(FULLMASK, c0, 2);
    u64 S23    = pk(s2, s3);
    u64 S23P2  = __shfl_down_sync(FULLMASK, S23, 2);
    float t = a + aP1;
    u64 tt = pk(t, t);
    H01 = fadd2(tt, pk(c3M1, c0P2));
    H23 = fadd2(ffma2(pk(c0, s2), m1, tt), S23P2);
}

__global__ __launch_bounds__(128, 4)
void vm_main(const float* __restrict__ Ig, const float* __restrict__ Jg,
             float* __restrict__ out) {
    // dynamic per-warp 13-slot row ring: [warp][img][slot][lane] float4
    extern __shared__ float4 ring[];

    const int wib  = threadIdx.x >> 5;              // 0..3 -> SMSP (balanced)
    const int lane = threadIdx.x & 31;
    const int W    = blockIdx.x * 4 + wib;
    const int sw   = W % NSTRIP;
    const int ck   = (W / NSTRIP) % NCH;
    const int b    = W / (NSTRIP * NCH);

    const int y0   = ck * CH;
    const int yend = min(y0 + CH, OH);
    const int rowOwnEnd = (yend == OH) ? HT : yend;
    const int gc   = 116 * sw - 4 + 4 * lane;

    const float* I = Ig + (size_t)b * HT * WD;
    const float* J = Jg + (size_t)b * HT * WD;

    const bool act = (lane >= 1 && lane <= 29);
    const bool gok = (gc >= 0) && (gc <= WD - 4);
    const int  szb = gok ? 16 : 0;
    const int  gcc = gok ? gc : 0;
    const bool safe = (y0 >= 1) && (yend + 11 <= HT);   // interior: no OOB rows

    float4* ringI = &ring[((wib * 2 + 0) * NSLOT) * 32];
    float4* ringJ = &ring[((wib * 2 + 1) * NSLOT) * 32];
    const uint32_t dI = smem_u32(&ringI[lane]);
    const uint32_t dJ = smem_u32(&ringJ[lane]);

    const u64 M1   = pk(-1.0f, -1.0f);
    const u64 NI81 = pk(-INV81, -INV81);
    const u64 EPS2 = pk(EPSF, EPSF);

    float cm[4], dm[4];
    #pragma unroll
    for (int k = 0; k < 4; k++) {
        cm[k] = (act && (gc + k) < OW) ? 1.f : 0.f;
        dm[k] = (act && (gc + k) < (WD - 1)) ? 1.f : 0.f;
    }
    const u64 ccmA = pk(cm[0], cm[1]), ccmB = pk(cm[2], cm[3]);
    const u64 dxmA = pk(dm[0], dm[1]), dxmB = pk(dm[2], dm[3]);

    // one-row issue (prologue), own commit group
    auto issue = [&](int r, int slot) {
        int sz = szb;
        long off = (long)r * WD + gcc;
        if (!safe && ((unsigned)r >= (unsigned)HT)) { sz = 0; off = 0; }
        cpa16(dI + slot * 512, I + off, sz);
        cpa16(dJ + slot * 512, J + off, sz);
        CPA_COMMIT();
    };
    // two-row issue (main pairs), single commit group
    auto issue2 = [&](int r0, int s0, int r1, int s1) {
        int sz0 = szb, sz1 = szb;
        long o0 = (long)r0 * WD + gcc, o1 = (long)r1 * WD + gcc;
        if (!safe) {
            if ((unsigned)r0 >= (unsigned)HT) { sz0 = 0; o0 = 0; }
            if ((unsigned)r1 >= (unsigned)HT) { sz1 = 0; o1 = 0; }
        }
        cpa16(dI + s0 * 512, I + o0, sz0);
        cpa16(dJ + s0 * 512, J + o0, sz0);
        cpa16(dI + s1 * 512, I + o1, sz1);
        cpa16(dJ + s1 * 512, J + o1, sz1);
        CPA_COMMIT();
    };

    u64 C[5][2];
    #pragma unroll
    for (int q = 0; q < 5; q++) { C[q][0] = 0ull; C[q][1] = 0ull; }

    u64 ipA = 0ull, ipB = 0ull;
    u64 aCC[2] = {0ull, 0ull}, aDX[2] = {0ull, 0ull}, aDY[2] = {0ull, 0ull};

    // ---- prologue: stage rows y0-1 .. y0+9 into slots 0..10 ----
    #pragma unroll 1
    for (int i = 0; i < 11; i++) issue(y0 - 1 + i, i);
    CPA_WAIT2();                      // rows y0-1..y0+7 (slots 0..8) landed

    #pragma unroll 1
    for (int i = 0; i < 9; i++) {
        const int r = y0 - 1 + i;
        float4 i4 = ringI[i * 32 + lane];
        float4 j4 = ringJ[i * 32 + lane];
        float inx1 = __shfl_down_sync(FULLMASK, i4.x, 1);
        u64 iA = pk(i4.x, i4.y), iB = pk(i4.z, i4.w);
        u64 jA = pk(j4.x, j4.y), jB = pk(j4.z, j4.w);

        if (act && r >= y0 && r < rowOwnEnd) {
            if (r >= 1) {
                u64 dA = fsub2(iA, ipA, M1); aDY[0] = ffma2(dA, dA, aDY[0]);
                u64 dB = fsub2(iB, ipB, M1); aDY[1] = ffma2(dB, dB, aDY[1]);
            }
            u64 sA = pk(i4.y, i4.z), sB = pk(i4.w, inx1);
            u64 eA = fmul2(fsub2(sA, iA, M1), dxmA); aDX[0] = ffma2(eA, eA, aDX[0]);
            u64 eB = fmul2(fsub2(sB, iB, M1), dxmB); aDX[1] = ffma2(eB, eB, aDX[1]);
        }
        C[0][0] = fadd2(C[0][0], iA);        C[0][1] = fadd2(C[0][1], iB);
        C[1][0] = fadd2(C[1][0], jA);        C[1][1] = fadd2(C[1][1], jB);
        C[2][0] = ffma2(iA, iA, C[2][0]);    C[2][1] = ffma2(iB, iB, C[2][1]);
        C[3][0] = ffma2(jA, jA, C[3][0]);    C[3][1] = ffma2(jB, jB, C[3][1]);
        C[4][0] = ffma2(iA, jA, C[4][0]);    C[4][1] = ffma2(iB, jB, C[4][1]);
        ipA = iA; ipB = iB;
    }

    // one output row given preloaded raws; hasm FIRST (covers callers' LDS latency)
    auto step = [&](float4 ni4, float4 nj4, float4 oi4, float4 oj4, int y) {
        u64 H[5][2];
        #pragma unroll
        for (int q = 0; q < 5; q++) hasm(C[q][0], C[q][1], M1, H[q][0], H[q][1]);

        {
            const u64 ccm[2] = {ccmA, ccmB};
            #pragma unroll
            for (int h = 0; h < 2; h++) {
                u64 SI = H[0][h], SJ = H[1][h], SII = H[2][h], SJJ = H[3][h], SIJ = H[4][h];
                u64 nsiw  = fmul2(SI, NI81);
                u64 cross = ffma2(nsiw, SJ, SIJ);
                u64 iv    = ffma2(nsiw, SI, SII);
                u64 njw   = fmul2(SJ, NI81);
                u64 jv    = ffma2(njw, SJ, SJJ);
                u64 den   = ffma2(iv, jv, EPS2);
                u64 num   = fmul2(fmul2(cross, cross), ccm[h]);
                float d0, d1; upk(den, d0, d1);
                u64 rc = pk(frcp(d0), frcp(d1));
                aCC[h] = ffma2(num, rc, aCC[h]);
            }
        }

        float inx1 = __shfl_down_sync(FULLMASK, ni4.x, 1);
        u64 niA = pk(ni4.x, ni4.y), niB = pk(ni4.z, ni4.w);
        u64 njA = pk(nj4.x, nj4.y), njB = pk(nj4.z, nj4.w);
        u64 oiA = pk(oi4.x, oi4.y), oiB = pk(oi4.z, oi4.w);
        u64 ojA = pk(oj4.x, oj4.y), ojB = pk(oj4.z, oj4.w);

        if (act && (y + 8) < rowOwnEnd) {
            u64 dA = fsub2(niA, ipA, M1); aDY[0] = ffma2(dA, dA, aDY[0]);
            u64 dB = fsub2(niB, ipB, M1); aDY[1] = ffma2(dB, dB, aDY[1]);
            u64 sA = pk(ni4.y, ni4.z), sB = pk(ni4.w, inx1);
            u64 eA = fmul2(fsub2(sA, niA, M1), dxmA); aDX[0] = ffma2(eA, eA, aDX[0]);
            u64 eB = fmul2(fsub2(sB, niB, M1), dxmB); aDX[1] = ffma2(eB, eB, aDX[1]);
        }

        // slide colsums (diff/sum factoring)
        u64 dIA = fsub2(niA, oiA, M1), sIA = fadd2(niA, oiA);
        u64 dIB = fsub2(niB, oiB, M1), sIB = fadd2(niB, oiB);
        u64 dJA = fsub2(njA, ojA, M1), sJA = fadd2(njA, ojA);
        u64 dJB = fsub2(njB, ojB, M1), sJB = fadd2(njB, ojB);
        C[0][0] = fadd2(C[0][0], dIA);       C[0][1] = fadd2(C[0][1], dIB);
        C[1][0] = fadd2(C[1][0], dJA);       C[1][1] = fadd2(C[1][1], dJB);
        C[2][0] = ffma2(dIA, sIA, C[2][0]);  C[2][1] = ffma2(dIB, sIB, C[2][1]);
        C[3][0] = ffma2(dJA, sJA, C[3][0]);  C[3][1] = ffma2(dJB, sJB, C[3][1]);
        C[4][0] = fsub2(ffma2(niA, njA, C[4][0]), fmul2(oiA, ojA), M1);
        C[4][1] = fsub2(ffma2(niB, njB, C[4][1]), fmul2(oiB, ojB), M1);

        ipA = niA; ipB = niB;
    };

    // ---- pair-unrolled main loop, loads hoisted over independent hasm ----
    // invariant at pair top: slots s..s+10 hold rows y-1..y+9; s+11, s+12 free
    int s = 0;
    #pragma unroll 1
    for (int y = y0; y < yend; y += 2) {
        int w0 = s + 11; if (w0 >= NSLOT) w0 -= NSLOT;
        int w1 = s + 12; if (w1 >= NSLOT) w1 -= NSLOT;
        issue2(y + 10, w0, y + 11, w1);   // one commit group for the pair
        CPA_WAIT1();                      // rows y+8, y+9 landed (pair group pends)

        int an = s + 9;  if (an >= NSLOT) an -= NSLOT;
        int bn = s + 10; if (bn >= NSLOT) bn -= NSLOT;
        int bo = s + 1;  if (bo >= NSLOT) bo -= NSLOT;

        // hoist: A's 4 rows + B's new rows issued before hasmA (in step A)
        float4 nAi = ringI[an * 32 + lane], nAj = ringJ[an * 32 + lane];
        float4 oAi = ringI[s  * 32 + lane], oAj = ringJ[s  * 32 + lane];
        float4 nBi = ringI[bn * 32 + lane], nBj = ringJ[bn * 32 + lane];

        step(nAi, nAj, oAi, oAj, y);

        float4 oBi = ringI[bo * 32 + lane], oBj = ringJ[bo * 32 + lane];
        step(nBi, nBj, oBi, oBj, y + 1);

        s += 2; if (s >= NSLOT) s -= NSLOT;
    }
    CPA_WAIT0();   // drain before exit

    // ---- reduce packed accumulators ----
    float acc_cc, acc_dx, acc_dy;
    {
        float x, yv;
        upk(aCC[0], x, yv); acc_cc = x + yv;
        upk(aCC[1], x, yv); acc_cc += x + yv;
        upk(aDX[0], x, yv); acc_dx = x + yv;
        upk(aDX[1], x, yv); acc_dx += x + yv;
        upk(aDY[0], x, yv); acc_dy = x + yv;
        upk(aDY[1], x, yv); acc_dy += x + yv;
    }

    #pragma unroll
    for (int off = 16; off > 0; off >>= 1) {
        acc_cc += __shfl_xor_sync(FULLMASK, acc_cc, off);
        acc_dx += __shfl_xor_sync(FULLMASK, acc_dx, off);
        acc_dy += __shfl_xor_sync(FULLMASK, acc_dy, off);
    }
    __shared__ float red[4][3];
    if (lane == 0) { red[wib][0] = acc_cc; red[wib][1] = acc_dx; red[wib][2] = acc_dy; }
    __syncthreads();
    if (threadIdx.x == 0) {
        float s0 = 0.f, s1 = 0.f, s2 = 0.f;
        #pragma unroll
        for (int i = 0; i < 4; i++) { s0 += red[i][0]; s1 += red[i][1]; s2 += red[i][2]; }
        atomicAdd(&g_cc, s0);
        atomicAdd(&g_dx, s1);
        atomicAdd(&g_dy, s2);

        __threadfence();
        unsigned t = atomicAdd(&g_cnt, 1u);
        if (t == (unsigned)(NBLK - 1)) {
            float cc = atomicAdd(&g_cc, 0.f);
            float dx = atomicAdd(&g_dx, 0.f);
            float dy = atomicAdd(&g_dy, 0.f);
            double ncc = 16.0 * 1018.0 * 1018.0;
            double nsm = 16.0 * 1023.0 * 1024.0;
            double val = -((double)cc / ncc) + 0.1 * 0.5 * ((double)dx + (double)dy) / nsm;
            out[0] = (float)val;
            g_cc = 0.f; g_dx = 0.f; g_dy = 0.f;
            g_cnt = 0u;
        }
    }
}

extern "C" void kernel_launch(void* const* d_in, const int* in_sizes, int n_in,
                              void* d_out, int out_size) {
    const float* y     = (const float*)d_in[0];
    const float* ytrue = (const float*)d_in[1];
    float* out = (float*)d_out;

    cudaFuncSetAttribute(vm_main, cudaFuncAttributeMaxDynamicSharedMemorySize, RING_BYTES);
    vm_main<<<NBLK, 128, RING_BYTES>>>(y, ytrue, out);
}

// round 15
// speedup vs baseline: 1.0477x; 1.0477x over previous
#include <cuda_runtime.h>
#include <cstdint>

typedef unsigned long long u64;

#define FULLMASK 0xffffffffu

namespace {
constexpr int HT = 1024, WD = 1024;   // input H, W
constexpr int OH = 1018, OW = 1018;   // conv output H, W (pad=1, k=9)
constexpr int NB = 16;                // batch
constexpr int NCH = 16;               // vertical chunks
constexpr int CH  = 64;               // rows per chunk (last chunk = 58; both even)
constexpr int NSTRIP = 9;             // horizontal strips of 116 outputs
constexpr int TOTW = NSTRIP * NCH * NB;   // 2304 warps
constexpr int NBLK = TOTW / 4;            // 576 blocks @ 4 blk/SM
constexpr int NSLOT = 13;             // ring slots: 11 live rows + 2 free write targets
constexpr int RING_BYTES = 4 * 2 * NSLOT * 32 * 16;   // 53,248 B/block (dynamic)
constexpr float INV81 = 1.0f / 81.0f;
constexpr float EPSF  = 2.220446049250313e-16f;  // np.finfo(float64).eps
}

__device__ float g_cc, g_dx, g_dy;
__device__ unsigned g_cnt;

// ---------- packed f32x2 helpers ----------
__device__ __forceinline__ u64 pk(float lo, float hi) {
    u64 r; asm("mov.b64 %0,{%1,%2};" : "=l"(r) : "f"(lo), "f"(hi)); return r;
}
__device__ __forceinline__ void upk(u64 v, float& lo, float& hi) {
    asm("mov.b64 {%0,%1},%2;" : "=f"(lo), "=f"(hi) : "l"(v));
}
__device__ __forceinline__ float lo32(u64 v) {   // register-aliasing, ~free
    return __uint_as_float((unsigned)v);
}
__device__ __forceinline__ u64 fadd2(u64 a, u64 b) {
    u64 r; asm("add.rn.f32x2 %0,%1,%2;" : "=l"(r) : "l"(a), "l"(b)); return r;
}
__device__ __forceinline__ u64 fmul2(u64 a, u64 b) {
    u64 r; asm("mul.rn.f32x2 %0,%1,%2;" : "=l"(r) : "l"(a), "l"(b)); return r;
}
__device__ __forceinline__ u64 ffma2(u64 a, u64 b, u64 c) {
    u64 r; asm("fma.rn.f32x2 %0,%1,%2,%3;" : "=l"(r) : "l"(a), "l"(b), "l"(c)); return r;
}
__device__ __forceinline__ u64 fsub2(u64 a, u64 b, u64 m1) { return ffma2(b, m1, a); }

__device__ __forceinline__ float frcp(float x) {
    float r; asm("rcp.approx.f32 %0,%1;" : "=f"(r) : "f"(x)); return r;
}

__device__ __forceinline__ uint32_t smem_u32(const void* p) {
    uint32_t a;
    asm("{ .reg .u64 t; cvta.to.shared.u64 t, %1; cvt.u32.u64 %0, t; }" : "=r"(a) : "l"(p));
    return a;
}
__device__ __forceinline__ void cpa16(uint32_t d, const float* s, int sz) {
    asm volatile("cp.async.cg.shared.global [%0], [%1], 16, %2;"
                 :: "r"(d), "l"(s), "r"(sz) : "memory");
}
#define CPA_COMMIT() asm volatile("cp.async.commit_group;" ::: "memory")
#define CPA_WAIT2()  asm volatile("cp.async.wait_group 2;" ::: "memory")
#define CPA_WAIT0()  asm volatile("cp.async.wait_group 0;" ::: "memory")

// horizontal 9-window sums (window = cols x-1..x+7) for 4 owned columns
__device__ __forceinline__ void hasm(u64 A, u64 B, u64 m1, u64& H01, u64& H23) {
    float c0, c1, c2, c3;
    upk(A, c0, c1); upk(B, c2, c3);
    float s2 = c0 + c1;
    float s3 = s2 + c2;
    float a  = s3 + c3;
    float aP1  = __shfl_down_sync(FULLMASK, a, 1);
    float c3M1 = __shfl_up_sync(FULLMASK, c3, 1);
    float c0P2 = __shfl_down_sync(FULLMASK, c0, 2);
    u64 S23    = pk(s2, s3);
    u64 S23P2  = __shfl_down_sync(FULLMASK, S23, 2);
    float t = a + aP1;
    u64 tt = pk(t, t);
    H01 = fadd2(tt, pk(c3M1, c0P2));
    H23 = fadd2(ffma2(pk(c0, s2), m1, tt), S23P2);
}

__global__ __launch_bounds__(128, 4)
void vm_main(const float* __restrict__ Ig, const float* __restrict__ Jg,
             float* __restrict__ out) {
    // dynamic per-warp 13-slot row ring: [warp][img][slot][lane] float4
    extern __shared__ float4 ring[];

    const int wib  = threadIdx.x >> 5;              // 0..3 -> SMSP (balanced)
    const int lane = threadIdx.x & 31;
    const int W    = blockIdx.x * 4 + wib;
    const int sw   = W % NSTRIP;
    const int ck   = (W / NSTRIP) % NCH;
    const int b    = W / (NSTRIP * NCH);

    const int y0   = ck * CH;
    const int yend = min(y0 + CH, OH);
    const int rowOwnEnd = (yend == OH) ? HT : yend;
    const int gc   = 116 * sw - 4 + 4 * lane;

    const float* I = Ig + (size_t)b * HT * WD;
    const float* J = Jg + (size_t)b * HT * WD;

    const bool act = (lane >= 1 && lane <= 29);
    const bool gok = (gc >= 0) && (gc <= WD - 4);
    const int  szb = gok ? 16 : 0;
    const int  gcc = gok ? gc : 0;
    const bool safe = (y0 >= 1) && (yend + 11 <= HT);   // interior: no OOB rows

    float4* ringI = &ring[((wib * 2 + 0) * NSLOT) * 32];
    float4* ringJ = &ring[((wib * 2 + 1) * NSLOT) * 32];
    const ulonglong2* RI = reinterpret_cast<const ulonglong2*>(ringI);
    const ulonglong2* RJ = reinterpret_cast<const ulonglong2*>(ringJ);
    const uint32_t dI = smem_u32(&ringI[lane]);
    const uint32_t dJ = smem_u32(&ringJ[lane]);

    const u64 M1   = pk(-1.0f, -1.0f);
    const u64 NI81 = pk(-INV81, -INV81);
    const u64 EPS2 = pk(EPSF, EPSF);

    float cm[4], dm[4];
    #pragma unroll
    for (int k = 0; k < 4; k++) {
        cm[k] = (act && (gc + k) < OW) ? 1.f : 0.f;
        dm[k] = (act && (gc + k) < (WD - 1)) ? 1.f : 0.f;
    }
    const u64 ccmA = pk(cm[0], cm[1]), ccmB = pk(cm[2], cm[3]);
    const u64 dxmA = pk(dm[0], dm[1]), dxmB = pk(dm[2], dm[3]);

    auto issue = [&](int r, int slot) {
        int sz = szb;
        long off = (long)r * WD + gcc;
        if (!safe && ((unsigned)r >= (unsigned)HT)) { sz = 0; off = 0; }
        cpa16(dI + slot * 512, I + off, sz);
        cpa16(dJ + slot * 512, J + off, sz);
        CPA_COMMIT();
    };

    u64 C[5][2];
    #pragma unroll
    for (int q = 0; q < 5; q++) { C[q][0] = 0ull; C[q][1] = 0ull; }

    u64 ipA = 0ull, ipB = 0ull;
    u64 aCC[2] = {0ull, 0ull}, aDX[2] = {0ull, 0ull}, aDY[2] = {0ull, 0ull};

    // ---- prologue: stage rows y0-1 .. y0+9 into slots 0..10 ----
    #pragma unroll 1
    for (int i = 0; i < 11; i++) issue(y0 - 1 + i, i);
    CPA_WAIT2();                      // rows y0-1..y0+7 (slots 0..8) landed

    #pragma unroll 1
    for (int i = 0; i < 9; i++) {
        const int r = y0 - 1 + i;
        ulonglong2 iv2 = RI[i * 32 + lane];
        ulonglong2 jv2 = RJ[i * 32 + lane];
        u64 iA = iv2.x, iB = iv2.y, jA = jv2.x, jB = jv2.y;
        float inx1 = __shfl_down_sync(FULLMASK, lo32(iA), 1);   // uniform shuffle

        if (act && r >= y0 && r < rowOwnEnd) {
            float n0, n1, n2, n3;
            upk(iA, n0, n1); upk(iB, n2, n3);
            if (r >= 1) {
                u64 dA = fsub2(iA, ipA, M1); aDY[0] = ffma2(dA, dA, aDY[0]);
                u64 dB = fsub2(iB, ipB, M1); aDY[1] = ffma2(dB, dB, aDY[1]);
            }
            u64 sA = pk(n1, n2), sB = pk(n3, inx1);
            u64 eA = fmul2(fsub2(sA, iA, M1), dxmA); aDX[0] = ffma2(eA, eA, aDX[0]);
            u64 eB = fmul2(fsub2(sB, iB, M1), dxmB); aDX[1] = ffma2(eB, eB, aDX[1]);
        }
        C[0][0] = fadd2(C[0][0], iA);        C[0][1] = fadd2(C[0][1], iB);
        C[1][0] = fadd2(C[1][0], jA);        C[1][1] = fadd2(C[1][1], jB);
        C[2][0] = ffma2(iA, iA, C[2][0]);    C[2][1] = ffma2(iB, iB, C[2][1]);
        C[3][0] = ffma2(jA, jA, C[3][0]);    C[3][1] = ffma2(jB, jB, C[3][1]);
        C[4][0] = ffma2(iA, jA, C[4][0]);    C[4][1] = ffma2(iB, jB, C[4][1]);
        ipA = iA; ipB = iB;
    }

    // one output row: new row y+8 at slot sn, old row y-1 at slot so
    auto step = [&](int y, int sn, int so) {
        ulonglong2 ni = RI[sn * 32 + lane];
        ulonglong2 nj = RJ[sn * 32 + lane];
        ulonglong2 oi = RI[so * 32 + lane];
        ulonglong2 oj = RJ[so * 32 + lane];
        u64 niA = ni.x, niB = ni.y, njA = nj.x, njB = nj.y;
        u64 oiA = oi.x, oiB = oi.y, ojA = oj.x, ojB = oj.y;
        float inx1 = __shfl_down_sync(FULLMASK, lo32(niA), 1);  // uniform shuffle

        u64 H[5][2];
        #pragma unroll
        for (int q = 0; q < 5; q++) hasm(C[q][0], C[q][1], M1, H[q][0], H[q][1]);

        {
            const u64 ccm[2] = {ccmA, ccmB};
            #pragma unroll
            for (int h = 0; h < 2; h++) {
                u64 SI = H[0][h], SJ = H[1][h], SII = H[2][h], SJJ = H[3][h], SIJ = H[4][h];
                u64 nsiw  = fmul2(SI, NI81);
                u64 cross = ffma2(nsiw, SJ, SIJ);
                u64 iv    = ffma2(nsiw, SI, SII);
                u64 njw   = fmul2(SJ, NI81);
                u64 jv    = ffma2(njw, SJ, SJJ);
                u64 den   = ffma2(iv, jv, EPS2);
                u64 num   = fmul2(fmul2(cross, cross), ccm[h]);
                float d0, d1; upk(den, d0, d1);
                u64 rc = pk(frcp(d0), frcp(d1));
                aCC[h] = ffma2(num, rc, aCC[h]);
            }
        }

        if (act && (y + 8) < rowOwnEnd) {
            float n0, n1, n2, n3;
            upk(niA, n0, n1); upk(niB, n2, n3);
            u64 dA = fsub2(niA, ipA, M1); aDY[0] = ffma2(dA, dA, aDY[0]);
            u64 dB = fsub2(niB, ipB, M1); aDY[1] = ffma2(dB, dB, aDY[1]);
            u64 sA = pk(n1, n2), sB = pk(n3, inx1);
            u64 eA = fmul2(fsub2(sA, niA, M1), dxmA); aDX[0] = ffma2(eA, eA, aDX[0]);
            u64 eB = fmul2(fsub2(sB, niB, M1), dxmB); aDX[1] = ffma2(eB, eB, aDX[1]);
        }

        // slide colsums (diff/sum factoring)
        u64 dIA = fsub2(niA, oiA, M1), sIA = fadd2(niA, oiA);
        u64 dIB = fsub2(niB, oiB, M1), sIB = fadd2(niB, oiB);
        u64 dJA = fsub2(njA, ojA, M1), sJA = fadd2(njA, ojA);
        u64 dJB = fsub2(njB, ojB, M1), sJB = fadd2(njB, ojB);
        C[0][0] = fadd2(C[0][0], dIA);       C[0][1] = fadd2(C[0][1], dIB);
        C[1][0] = fadd2(C[1][0], dJA);       C[1][1] = fadd2(C[1][1], dJB);
        C[2][0] = ffma2(dIA, sIA, C[2][0]);  C[2][1] = ffma2(dIB, sIB, C[2][1]);
        C[3][0] = ffma2(dJA, sJA, C[3][0]);  C[3][1] = ffma2(dJB, sJB, C[3][1]);
        C[4][0] = fsub2(ffma2(niA, njA, C[4][0]), fmul2(oiA, ojA), M1);
        C[4][1] = fsub2(ffma2(niB, njB, C[4][1]), fmul2(oiB, ojB), M1);

        ipA = niA; ipB = niB;
    };

    // ---- pair-unrolled main loop (race-free with 13 slots) ----
    // invariant at pair top: slots s..s+10 hold rows y-1..y+9; s+11, s+12 free
    int s = 0;
    #pragma unroll 1
    for (int y = y0; y < yend; y += 2) {
        int w0 = s + 11; if (w0 >= NSLOT) w0 -= NSLOT;
        int w1 = s + 12; if (w1 >= NSLOT) w1 -= NSLOT;
        issue(y + 10, w0);            // -> free slot
        issue(y + 11, w1);            // -> free slot
        CPA_WAIT2();                  // rows y+8, y+9 landed (2 newest may pend)

        int an = s + 9;  if (an >= NSLOT) an -= NSLOT;
        int bn = s + 10; if (bn >= NSLOT) bn -= NSLOT;
        int bo = s + 1;  if (bo >= NSLOT) bo -= NSLOT;
        step(y,     an, s);           // new y+8, old y-1
        step(y + 1, bn, bo);          // new y+9, old y
        s += 2; if (s >= NSLOT) s -= NSLOT;
    }
    CPA_WAIT0();   // drain before exit

    // ---- reduce packed accumulators ----
    float acc_cc, acc_dx, acc_dy;
    {
        float x, yv;
        upk(aCC[0], x, yv); acc_cc = x + yv;
        upk(aCC[1], x, yv); acc_cc += x + yv;
        upk(aDX[0], x, yv); acc_dx = x + yv;
        upk(aDX[1], x, yv); acc_dx += x + yv;
        upk(aDY[0], x, yv); acc_dy = x + yv;
        upk(aDY[1], x, yv); acc_dy += x + yv;
    }

    #pragma unroll
    for (int off = 16; off > 0; off >>= 1) {
        acc_cc += __shfl_xor_sync(FULLMASK, acc_cc, off);
        acc_dx += __shfl_xor_sync(FULLMASK, acc_dx, off);
        acc_dy += __shfl_xor_sync(FULLMASK, acc_dy, off);
    }
    __shared__ float red[4][3];
    if (lane == 0) { red[wib][0] = acc_cc; red[wib][1] = acc_dx; red[wib][2] = acc_dy; }
    __syncthreads();
    if (threadIdx.x == 0) {
        float s0 = 0.f, s1 = 0.f, s2 = 0.f;
        #pragma unroll
        for (int i = 0; i < 4; i++) { s0 += red[i][0]; s1 += red[i][1]; s2 += red[i][2]; }
        atomicAdd(&g_cc, s0);
        atomicAdd(&g_dx, s1);
        atomicAdd(&g_dy, s2);

        __threadfence();
        unsigned t = atomicAdd(&g_cnt, 1u);
        if (t == (unsigned)(NBLK - 1)) {
            float cc = atomicAdd(&g_cc, 0.f);
            float dx = atomicAdd(&g_dx, 0.f);
            float dy = atomicAdd(&g_dy, 0.f);
            double ncc = 16.0 * 1018.0 * 1018.0;
            double nsm = 16.0 * 1023.0 * 1024.0;
            double val = -((double)cc / ncc) + 0.1 * 0.5 * ((double)dx + (double)dy) / nsm;
            out[0] = (float)val;
            g_cc = 0.f; g_dx = 0.f; g_dy = 0.f;
            g_cnt = 0u;
        }
    }
}

extern "C" void kernel_launch(void* const* d_in, const int* in_sizes, int n_in,
                              void* d_out, int out_size) {
    const float* y     = (const float*)d_in[0];
    const float* ytrue = (const float*)d_in[1];
    float* out = (float*)d_out;

    cudaFuncSetAttribute(vm_main, cudaFuncAttributeMaxDynamicSharedMemorySize, RING_BYTES);
    vm_main<<<NBLK, 128, RING_BYTES>>>(y, ytrue, out);
}